// round 6
// baseline (speedup 1.0000x reference)
#include <cuda_runtime.h>
#include <math.h>

#define D_MODEL   1024
#define SEQ_LEN   32768
#define NBLK_A    1024                  // phase-A blocks
#define LPB       32                    // l's per block (1024*32 = 32768)
#define LPW       4                     // l's per warp (8 warps/block)

#define TWO_PI    6.283185307179586f
#define INV_2PI   0.15915494309189535f
#define MAGIC     12582912.0f           // 1.5 * 2^23
#define C1_2PI    6.28318548202514648f  // fl32(2*pi)
#define INV1023   (1.0f / 1023.0f)

typedef unsigned long long ull;

// Scratch (device globals; no allocation in kernel_launch)
// g_part[slice][i], i = m*32 + k packs (d=32k+2m, d=32k+2m+1), sign-twisted.
__device__ ull g_part[NBLK_A * 512];               // 4 MB
__device__ __align__(16) float g_signal[D_MODEL];

// ---------------- packed f32x2 helpers --------------------------------------
__device__ __forceinline__ ull fma2(ull a, ull b, ull c) {
    ull d; asm("fma.rn.f32x2 %0,%1,%2,%3;" : "=l"(d) : "l"(a), "l"(b), "l"(c)); return d;
}
__device__ __forceinline__ ull add2(ull a, ull b) {
    ull d; asm("add.rn.f32x2 %0,%1,%2;" : "=l"(d) : "l"(a), "l"(b)); return d;
}
__device__ __forceinline__ ull pk2(float lo, float hi) {
    ull d; asm("mov.b64 %0,{%1,%2};" : "=l"(d) : "f"(lo), "f"(hi)); return d;
}
__device__ __forceinline__ float2 unpk(ull v) {
    float2 r; asm("mov.b64 {%0,%1},%2;" : "=f"(r.x), "=f"(r.y) : "l"(v)); return r;
}

// ---------------------------------------------------------------------------
// Kernel A: sin partial sums, packed-pair Chebyshev recurrence over d.
// Warp covers all 1024 d for LPW l's; lane k owns d=32k..32k+31 as 16 pairs.
// Sign-twisted sequence a_m = sigma_m * v_m makes every step a plain fma2
// with statically alternating +/-c2; sigma is undone in kernel B.
// ---------------------------------------------------------------------------
__global__ void __launch_bounds__(256)
sinsum_kernel(const float* __restrict__ inputs) {
    __shared__ float4 co[LPB];        // (a, a*log1p(l), 2cos(dl), 2cos(2dl))
    __shared__ ull    sred[8 * 512];  // 32KB packed cross-warp buffer

    const int tid = threadIdx.x;
    const int w   = tid >> 5;
    const int k   = tid & 31;

    if (tid < LPB) {
        const int l = blockIdx.x * LPB + tid;
        float x  = inputs[l];
        float a  = TWO_PI * x;
        float p  = log1pf((float)l);
        float dl = a * INV1023;
        float d2 = dl * dl;
        float u2 = 4.0f * d2;                         // (2*dl)^2
        // 2cos(z) = 2 + z^2*(-1 + z^2*(1/12 - z^2/360))
        float c  = fmaf(d2, fmaf(d2, fmaf(d2, -(1.0f/360.0f), (1.0f/12.0f)), -1.0f), 2.0f);
        float c2 = fmaf(u2, fmaf(u2, fmaf(u2, -(1.0f/360.0f), (1.0f/12.0f)), -1.0f), 2.0f);
        co[tid]  = make_float4(a, a * p, c, c2);
    }
    __syncthreads();

    const float tk = (float)(32 * k) * INV1023;

    ull acc[16];
#pragma unroll
    for (int m = 0; m < 16; ++m) acc[m] = 0ull;

#pragma unroll 1
    for (int j = 0; j < LPW; ++j) {
        float4 C = co[w * LPW + j];                   // LDS.128 broadcast

        // Seeds: exact 2pi reduction once, neighbor via +dl.
        float phi = fmaf(C.x, tk, C.y);
        float y   = fmaf(phi, INV_2PI, MAGIC);
        float q   = y - MAGIC;
        float r0  = fmaf(q, -C1_2PI, phi);
        float dl  = C.x * INV1023;
        float s0  = __sinf(r0);
        float s1  = __sinf(r0 + dl);
        float s2  = fmaf(C.z, s1, -s0);
        float s3  = fmaf(C.z, s2, -s1);

        ull a0 = pk2(s0, s1);                         // = v0 (sigma=+)
        ull a1 = pk2(s2, s3);                         // = v1 (sigma=+)
        float nc2s = -C.w;
        ull c2p  = pk2(C.w, C.w);
        ull nc2p = pk2(nc2s, nc2s);

        acc[0] = add2(acc[0], a0);
        acc[1] = add2(acc[1], a1);

#pragma unroll
        for (int m = 2; m < 16; ++m) {
            // a_m = fma2(m odd ? +c2 : -c2, a_{m-1}, a_{m-2})
            ull an = fma2((m & 1) ? c2p : nc2p, a1, a0);
            acc[m] = add2(acc[m], an);
            a0 = a1; a1 = an;
        }
    }

    // Epilogue: packed cross-warp reduce (no scalar transpose).
#pragma unroll
    for (int m = 0; m < 16; ++m)
        sred[w * 512 + m * 32 + k] = acc[m];
    __syncthreads();

#pragma unroll
    for (int rep = 0; rep < 2; ++rep) {
        const int i = tid + rep * 256;
        ull s = sred[i];
#pragma unroll
        for (int ww = 1; ww < 8; ++ww)
            s = add2(s, sred[ww * 512 + i]);
        g_part[blockIdx.x * 512 + i] = s;             // STG.64 coalesced
    }
}

// ---------------------------------------------------------------------------
// Kernel B: reduce 1024 slices per packed column, undo sigma, emit signal.
// 64 blocks x 256 threads; block owns 8 columns.
// ---------------------------------------------------------------------------
__global__ void reduce_kernel() {
    __shared__ ull sb[32][8];
    const int tid = threadIdx.x;
    const int col = blockIdx.x * 8 + (tid & 7);
    const int sl0 = tid >> 3;                         // 0..31

    ull s = 0ull;
#pragma unroll 8
    for (int j = 0; j < 32; ++j)
        s = add2(s, g_part[(sl0 + 32 * j) * 512 + col]);
    sb[sl0][tid & 7] = s;
    __syncthreads();

    if (tid < 8) {
        ull tot = sb[0][tid];
#pragma unroll
        for (int r = 1; r < 32; ++r) tot = add2(tot, sb[r][tid]);
        const int i  = blockIdx.x * 8 + tid;
        const int m  = i >> 5;
        const int kk = i & 31;
        const float sg = ((m >> 1) & 1) ? -1.0f : 1.0f;   // sigma_m
        float2 v = unpk(tot);
        const int d0 = 32 * kk + 2 * m;
        g_signal[d0]     = sg * v.x;
        g_signal[d0 + 1] = sg * v.y;
    }
}

// ---------------------------------------------------------------------------
// Kernel C: GEMV out = signal @ W^T + b. 256 blocks x 128 thr, warp per row.
// ---------------------------------------------------------------------------
__global__ void gemv_kernel(const float* __restrict__ W,
                            const float* __restrict__ bias,
                            float* __restrict__ out) {
    __shared__ __align__(16) float ssig[D_MODEL];

    const int tid = threadIdx.x;
#pragma unroll
    for (int i = tid; i < D_MODEL / 4; i += 128)
        ((float4*)ssig)[i] = ((const float4*)g_signal)[i];
    __syncthreads();

    const int warp = tid >> 5;
    const int lane = tid & 31;
    const int row  = blockIdx.x * 4 + warp;

    const float4* w4 = (const float4*)(W + row * D_MODEL);
    float acc = 0.0f;
#pragma unroll
    for (int kk = lane; kk < D_MODEL / 4; kk += 32) {
        float4 wv = w4[kk];
        float4 sv = ((const float4*)ssig)[kk];
        acc = fmaf(wv.x, sv.x, acc);
        acc = fmaf(wv.y, sv.y, acc);
        acc = fmaf(wv.z, sv.z, acc);
        acc = fmaf(wv.w, sv.w, acc);
    }
#pragma unroll
    for (int off = 16; off > 0; off >>= 1)
        acc += __shfl_down_sync(0xffffffffu, acc, off);

    if (lane == 0) out[row] = acc + bias[row];
}

// ---------------------------------------------------------------------------
extern "C" void kernel_launch(void* const* d_in, const int* in_sizes, int n_in,
                              void* d_out, int out_size) {
    const float* inputs = (const float*)d_in[0];   // [32768]
    const float* W      = (const float*)d_in[1];   // [1024,1024]
    const float* b      = (const float*)d_in[2];   // [1024]
    float*       out    = (float*)d_out;           // [1024]

    sinsum_kernel<<<NBLK_A, 256>>>(inputs);
    reduce_kernel<<<64, 256>>>();
    gemv_kernel<<<D_MODEL / 4, 128>>>(W, b, out);
    (void)in_sizes; (void)n_in; (void)out_size;
}